// round 5
// baseline (speedup 1.0000x reference)
#include <cuda_runtime.h>
#include <cuda_bf16.h>
#include <math.h>
#include <stdint.h>

// Problem constants
#define T_TOK 2048
#define H_DIM 1024
#define I_DIM 512
#define NE    16
#define TK    4
#define NPAIR (T_TOK * TK)   // 8192

// ---------------- scratch (device globals; no allocation) ----------------
__device__ int   g_offsets[NE + 1];
__device__ int   g_ids[NPAIR];
__device__ float g_wt[NPAIR];
__device__ int   g_slot[NPAIR];

__device__ __align__(16) __nv_bfloat16 g_xhi[T_TOK * H_DIM];
__device__ __align__(16) __nv_bfloat16 g_xlo[T_TOK * H_DIM];
__device__ __align__(16) __nv_bfloat16 g_wu_hi[NE * I_DIM * H_DIM];
__device__ __align__(16) __nv_bfloat16 g_wu_lo[NE * I_DIM * H_DIM];
__device__ __align__(16) __nv_bfloat16 g_wg_hi[NE * I_DIM * H_DIM];
__device__ __align__(16) __nv_bfloat16 g_wg_lo[NE * I_DIM * H_DIM];
__device__ __align__(16) __nv_bfloat16 g_wd_hi[NE * H_DIM * I_DIM];
__device__ __align__(16) __nv_bfloat16 g_wd_lo[NE * H_DIM * I_DIM];
__device__ __align__(16) __nv_bfloat16 g_hhi[(size_t)NPAIR * I_DIM];
__device__ __align__(16) __nv_bfloat16 g_hlo[(size_t)NPAIR * I_DIM];
__device__ __align__(16) float g_part[(size_t)NPAIR * H_DIM];   // 32 MB

// ---------------- helpers ----------------
__device__ __forceinline__ uint32_t smem_u32(const void* p) {
    uint32_t a;
    asm("{ .reg .u64 t; cvta.to.shared.u64 t, %1; cvt.u32.u64 %0, t; }" : "=r"(a) : "l"(p));
    return a;
}
__device__ __forceinline__ void cp_async16(uint32_t dst, const void* src) {
    asm volatile("cp.async.cg.shared.global [%0], [%1], 16;" :: "r"(dst), "l"(src));
}
__device__ __forceinline__ void ldmx4(uint32_t r[4], uint32_t addr) {
    asm volatile("ldmatrix.sync.aligned.m8n8.x4.shared.b16 {%0,%1,%2,%3}, [%4];"
                 : "=r"(r[0]), "=r"(r[1]), "=r"(r[2]), "=r"(r[3]) : "r"(addr));
}
__device__ __forceinline__ void mma16816(float d[4], const uint32_t a[4], uint32_t b0, uint32_t b1) {
    asm("mma.sync.aligned.m16n8k16.row.col.f32.bf16.bf16.f32 "
        "{%0,%1,%2,%3}, {%4,%5,%6,%7}, {%8,%9}, {%0,%1,%2,%3};"
        : "+f"(d[0]), "+f"(d[1]), "+f"(d[2]), "+f"(d[3])
        : "r"(a[0]), "r"(a[1]), "r"(a[2]), "r"(a[3]), "r"(b0), "r"(b1));
}
#define SWZ(o) ((o) ^ (((o) >> 3) & 0x70))

// ---------------- kernel: fused routing (router + scan + scatter), 1 block ----------------
__global__ void __launch_bounds__(1024) routing_kernel(const float* __restrict__ logits) {
    __shared__ int s_cnt[NE], s_cur[NE], s_off[NE + 1];
    int tid = threadIdx.x;
    if (tid < NE) { s_cnt[tid] = 0; s_cur[tid] = 0; }
    __syncthreads();

    for (int t = tid; t < T_TOK; t += 1024) {
        float l[NE];
#pragma unroll
        for (int e = 0; e < NE; e++) l[e] = logits[t * NE + e];
        int ids[TK]; float vals[TK];
        unsigned mask = 0;
#pragma unroll
        for (int k = 0; k < TK; k++) {
            float best = -1e30f; int bi = 0;
#pragma unroll
            for (int e = 0; e < NE; e++)
                if (!((mask >> e) & 1u) && l[e] > best) { best = l[e]; bi = e; }
            ids[k] = bi; vals[k] = best; mask |= (1u << bi);
        }
        float m = vals[0];
        float w[TK]; float s = 0.f;
#pragma unroll
        for (int k = 0; k < TK; k++) { w[k] = expf(vals[k] - m); s += w[k]; }
        float inv = 1.f / s;
#pragma unroll
        for (int k = 0; k < TK; k++) {
            g_ids[t * TK + k] = ids[k];
            g_wt[t * TK + k]  = w[k] * inv;
            atomicAdd(&s_cnt[ids[k]], 1);
        }
    }
    __syncthreads();
    if (tid == 0) {
        int acc = 0;
        s_off[0] = 0; g_offsets[0] = 0;
#pragma unroll
        for (int e = 0; e < NE; e++) {
            acc += s_cnt[e];
            s_off[e + 1] = acc;
            g_offsets[e + 1] = acc;
        }
    }
    __syncthreads();
    for (int t = tid; t < T_TOK; t += 1024) {
#pragma unroll
        for (int k = 0; k < TK; k++) {
            int e = g_ids[t * TK + k];
            int pos = s_off[e] + atomicAdd(&s_cur[e], 1);
            g_slot[pos] = t * TK + k;
        }
    }
}

// ---------------- kernel: fused fp32 -> bf16 hi/lo split for all 4 tensors ----------------
#define NX4 (T_TOK * H_DIM / 4)
#define NW4 (NE * I_DIM * H_DIM / 4)
__global__ void conv_all_kernel(const float4* __restrict__ x,
                                const float4* __restrict__ wu,
                                const float4* __restrict__ wg,
                                const float4* __restrict__ wd) {
    int i = blockIdx.x * blockDim.x + threadIdx.x;
    const float4* src; __nv_bfloat16* hi; __nv_bfloat16* lo; int idx;
    if (i < NX4)                { src = x;  hi = g_xhi;  lo = g_xlo;  idx = i; }
    else if (i < NX4 + NW4)     { src = wu; hi = g_wu_hi; lo = g_wu_lo; idx = i - NX4; }
    else if (i < NX4 + 2 * NW4) { src = wg; hi = g_wg_hi; lo = g_wg_lo; idx = i - NX4 - NW4; }
    else if (i < NX4 + 3 * NW4) { src = wd; hi = g_wd_hi; lo = g_wd_lo; idx = i - NX4 - 2 * NW4; }
    else return;
    float4 v = src[idx];
    __nv_bfloat16 h0 = __float2bfloat16_rn(v.x);
    __nv_bfloat16 h1 = __float2bfloat16_rn(v.y);
    __nv_bfloat16 h2 = __float2bfloat16_rn(v.z);
    __nv_bfloat16 h3 = __float2bfloat16_rn(v.w);
    __nv_bfloat16 l0 = __float2bfloat16_rn(v.x - __bfloat162float(h0));
    __nv_bfloat16 l1 = __float2bfloat16_rn(v.y - __bfloat162float(h1));
    __nv_bfloat16 l2 = __float2bfloat16_rn(v.z - __bfloat162float(h2));
    __nv_bfloat16 l3 = __float2bfloat16_rn(v.w - __bfloat162float(h3));
    *(__nv_bfloat162*)&hi[4 * idx + 0] = __halves2bfloat162(h0, h1);
    *(__nv_bfloat162*)&hi[4 * idx + 2] = __halves2bfloat162(h2, h3);
    *(__nv_bfloat162*)&lo[4 * idx + 0] = __halves2bfloat162(l0, l1);
    *(__nv_bfloat162*)&lo[4 * idx + 2] = __halves2bfloat162(l2, l3);
}

// ============================================================================
// pass1: grouped HMMA GEMM, CTA 128x64, K=1024, fused up+gate, 3-term split
// 3-stage cp.async pipeline, one __syncthreads per chunk
// ============================================================================
#define P1_ATILE 16384                          // 128 rows x 128B
#define P1_BTILE 8192                           // 64 rows x 128B
#define P1_STAGE (2 * P1_ATILE + 4 * P1_BTILE)  // 65536
#define P1_NSTG  3
#define P1_SMEM  (1024 + P1_NSTG * P1_STAGE)    // 197632
#define P1_NC    16

__device__ __forceinline__ void p1_load(uint32_t st, int k0, int e, int n0,
                                        const int* s_tok, int tid) {
    for (int i = tid; i < 2048; i += 256) {
        int sel = i >> 10, r = (i >> 3) & 127, q = i & 7;
        const __nv_bfloat16* src = (sel ? g_xlo : g_xhi) + (size_t)s_tok[r] * H_DIM + k0 + q * 8;
        cp_async16(st + sel * P1_ATILE + SWZ(r * 128 + q * 16), src);
    }
    for (int i = tid; i < 2048; i += 256) {
        int sel = i >> 9, r = (i >> 3) & 63, q = i & 7;
        const __nv_bfloat16* base =
            (sel == 0) ? g_wu_hi : (sel == 1) ? g_wu_lo : (sel == 2) ? g_wg_hi : g_wg_lo;
        const __nv_bfloat16* src = base + ((size_t)e * I_DIM + n0 + r) * H_DIM + k0 + q * 8;
        cp_async16(st + 2 * P1_ATILE + sel * P1_BTILE + SWZ(r * 128 + q * 16), src);
    }
    asm volatile("cp.async.commit_group;" ::: "memory");
}

__global__ void __launch_bounds__(256, 1) pass1_mma() {
    int e     = blockIdx.z;
    int mBase = g_offsets[e];
    int mEnd  = g_offsets[e + 1];
    int m0    = mBase + blockIdx.y * 128;
    if (m0 >= mEnd) return;
    int n0 = blockIdx.x * 64;

    extern __shared__ char smem[];
    int*   s_tok = (int*)smem;            // 128 ints
    float* s_wt  = (float*)(smem + 512);  // 128 floats
    uint32_t tb  = smem_u32(smem + 1024);

    int tid = threadIdx.x, wid = tid >> 5, lane = tid & 31;
    for (int r = tid; r < 128; r += 256) {
        int gm = m0 + r;
        int slot = (gm < mEnd) ? g_slot[gm] : g_slot[mBase];
        s_tok[r] = slot >> 2;
        s_wt[r]  = g_wt[slot];
    }
    __syncthreads();

    float accU[2][4][4], accG[2][4][4];
#pragma unroll
    for (int a = 0; a < 2; a++)
#pragma unroll
        for (int b = 0; b < 4; b++)
#pragma unroll
            for (int c = 0; c < 4; c++) { accU[a][b][c] = 0.f; accG[a][b][c] = 0.f; }

    int wm = (wid >> 1) * 32;     // warp m offset (0..96)
    int wn = (wid & 1) * 32;      // warp n offset (0 or 32)
    int lgrp = lane >> 3, lr = lane & 7;
    int rowA = wm + (lgrp & 1) * 8 + lr;
    int rowB = wn + (lgrp >> 1) * 8 + lr;

    // prologue: stages 0 and 1
    p1_load(tb, 0, e, n0, s_tok, tid);
    p1_load(tb + P1_STAGE, 64, e, n0, s_tok, tid);

    for (int c = 0; c < P1_NC; c++) {
        if (c + 1 < P1_NC) asm volatile("cp.async.wait_group 1;" ::: "memory");
        else               asm volatile("cp.async.wait_group 0;" ::: "memory");
        __syncthreads();
        if (c + 2 < P1_NC)
            p1_load(tb + ((c + 2) % P1_NSTG) * P1_STAGE, (c + 2) * 64, e, n0, s_tok, tid);

        uint32_t st  = tb + (c % P1_NSTG) * P1_STAGE;
        uint32_t aHi = st, aLo = st + P1_ATILE;
        uint32_t bU0 = st + 2 * P1_ATILE;            // up hi
        uint32_t bU1 = bU0 + P1_BTILE;               // up lo
        uint32_t bG0 = bU0 + 2 * P1_BTILE;           // gate hi
        uint32_t bG1 = bU0 + 3 * P1_BTILE;           // gate lo

#pragma unroll
        for (int s = 0; s < 4; s++) {
            int kaB = (s * 16 + (lgrp >> 1) * 8) * 2;   // A k byte offset
            int kbB = (s * 16 + (lgrp & 1) * 8) * 2;    // B k byte offset
            uint32_t Ah[2][4], Al[2][4];
            ldmx4(Ah[0], aHi + SWZ(rowA * 128 + kaB));
            ldmx4(Ah[1], aHi + SWZ((rowA + 16) * 128 + kaB));
            ldmx4(Al[0], aLo + SWZ(rowA * 128 + kaB));
            ldmx4(Al[1], aLo + SWZ((rowA + 16) * 128 + kaB));
            uint32_t Uh[2][4], Ul[2][4], Gh[2][4], Gl[2][4];
#pragma unroll
            for (int p = 0; p < 2; p++) {
                uint32_t off = SWZ((rowB + p * 16) * 128 + kbB);
                ldmx4(Uh[p], bU0 + off);
                ldmx4(Ul[p], bU1 + off);
                ldmx4(Gh[p], bG0 + off);
                ldmx4(Gl[p], bG1 + off);
            }
            // term-major ordering: 16 independent MMAs between accumulator reuses
#pragma unroll
            for (int mi = 0; mi < 2; mi++)
#pragma unroll
                for (int nf = 0; nf < 4; nf++) {
                    int p = nf >> 1, h = (nf & 1) * 2;
                    mma16816(accU[mi][nf], Ah[mi], Uh[p][h], Uh[p][h + 1]);
                    mma16816(accG[mi][nf], Ah[mi], Gh[p][h], Gh[p][h + 1]);
                }
#pragma unroll
            for (int mi = 0; mi < 2; mi++)
#pragma unroll
                for (int nf = 0; nf < 4; nf++) {
                    int p = nf >> 1, h = (nf & 1) * 2;
                    mma16816(accU[mi][nf], Al[mi], Uh[p][h], Uh[p][h + 1]);
                    mma16816(accG[mi][nf], Al[mi], Gh[p][h], Gh[p][h + 1]);
                }
#pragma unroll
            for (int mi = 0; mi < 2; mi++)
#pragma unroll
                for (int nf = 0; nf < 4; nf++) {
                    int p = nf >> 1, h = (nf & 1) * 2;
                    mma16816(accU[mi][nf], Ah[mi], Ul[p][h], Ul[p][h + 1]);
                    mma16816(accG[mi][nf], Ah[mi], Gl[p][h], Gl[p][h + 1]);
                }
        }
    }

    // ---- epilogue: h = w * silu(w*g) * (w*u), re-split into bf16 hi/lo ----
    int r4 = lane >> 2, c2 = (lane & 3) * 2;
#pragma unroll
    for (int mi = 0; mi < 2; mi++) {
#pragma unroll
        for (int half = 0; half < 2; half++) {
            int row = wm + mi * 16 + half * 8 + r4;
            int gm  = m0 + row;
            if (gm >= mEnd) continue;
            float w = s_wt[row];
#pragma unroll
            for (int nf = 0; nf < 4; nf++) {
                int col = n0 + wn + nf * 8 + c2;
                float u0 = w * accU[mi][nf][half * 2 + 0];
                float u1 = w * accU[mi][nf][half * 2 + 1];
                float gg0 = w * accG[mi][nf][half * 2 + 0];
                float gg1 = w * accG[mi][nf][half * 2 + 1];
                float r0 = w * (gg0 / (1.f + expf(-gg0))) * u0;
                float r1 = w * (gg1 / (1.f + expf(-gg1))) * u1;
                __nv_bfloat16 h0 = __float2bfloat16_rn(r0);
                __nv_bfloat16 h1 = __float2bfloat16_rn(r1);
                __nv_bfloat16 l0 = __float2bfloat16_rn(r0 - __bfloat162float(h0));
                __nv_bfloat16 l1 = __float2bfloat16_rn(r1 - __bfloat162float(h1));
                *(__nv_bfloat162*)&g_hhi[(size_t)gm * I_DIM + col] = __halves2bfloat162(h0, h1);
                *(__nv_bfloat162*)&g_hlo[(size_t)gm * I_DIM + col] = __halves2bfloat162(l0, l1);
            }
        }
    }
}

// ============================================================================
// pass2: grouped HMMA GEMM h @ w_down^T, CTA 128x64, K=512, 3-term split
// ============================================================================
#define P2_ATILE 16384
#define P2_BTILE 8192
#define P2_STAGE (2 * P2_ATILE + 2 * P2_BTILE)  // 49152
#define P2_NSTG  3
#define P2_SMEM  (1024 + P2_NSTG * P2_STAGE)    // 148480
#define P2_NC    8

__device__ __forceinline__ void p2_load(uint32_t st, int k0, int e, int n0,
                                        const int* s_row, int tid) {
    for (int i = tid; i < 2048; i += 256) {
        int sel = i >> 10, r = (i >> 3) & 127, q = i & 7;
        const __nv_bfloat16* src = (sel ? g_hlo : g_hhi) + (size_t)s_row[r] * I_DIM + k0 + q * 8;
        cp_async16(st + sel * P2_ATILE + SWZ(r * 128 + q * 16), src);
    }
    for (int i = tid; i < 1024; i += 256) {
        int sel = i >> 9, r = (i >> 3) & 63, q = i & 7;
        const __nv_bfloat16* base = sel ? g_wd_lo : g_wd_hi;
        const __nv_bfloat16* src = base + ((size_t)e * H_DIM + n0 + r) * I_DIM + k0 + q * 8;
        cp_async16(st + 2 * P2_ATILE + sel * P2_BTILE + SWZ(r * 128 + q * 16), src);
    }
    asm volatile("cp.async.commit_group;" ::: "memory");
}

__global__ void __launch_bounds__(256, 1) pass2_mma() {
    int e     = blockIdx.z;
    int mBase = g_offsets[e];
    int mEnd  = g_offsets[e + 1];
    int m0    = mBase + blockIdx.y * 128;
    if (m0 >= mEnd) return;
    int n0 = blockIdx.x * 64;

    extern __shared__ char smem[];
    int* s_row  = (int*)smem;
    int* s_slot = (int*)(smem + 512);
    uint32_t tb = smem_u32(smem + 1024);

    int tid = threadIdx.x, wid = tid >> 5, lane = tid & 31;
    for (int r = tid; r < 128; r += 256) {
        int gm = m0 + r;
        s_row[r]  = (gm < mEnd) ? gm : mBase;
        s_slot[r] = (gm < mEnd) ? g_slot[gm] : 0;
    }
    __syncthreads();

    float acc[2][4][4];
#pragma unroll
    for (int a = 0; a < 2; a++)
#pragma unroll
        for (int b = 0; b < 4; b++)
#pragma unroll
            for (int c = 0; c < 4; c++) acc[a][b][c] = 0.f;

    int wm = (wid >> 1) * 32;
    int wn = (wid & 1) * 32;
    int lgrp = lane >> 3, lr = lane & 7;
    int rowA = wm + (lgrp & 1) * 8 + lr;
    int rowB = wn + (lgrp >> 1) * 8 + lr;

    p2_load(tb, 0, e, n0, s_row, tid);
    p2_load(tb + P2_STAGE, 64, e, n0, s_row, tid);

    for (int c = 0; c < P2_NC; c++) {
        if (c + 1 < P2_NC) asm volatile("cp.async.wait_group 1;" ::: "memory");
        else               asm volatile("cp.async.wait_group 0;" ::: "memory");
        __syncthreads();
        if (c + 2 < P2_NC)
            p2_load(tb + ((c + 2) % P2_NSTG) * P2_STAGE, (c + 2) * 64, e, n0, s_row, tid);

        uint32_t st  = tb + (c % P2_NSTG) * P2_STAGE;
        uint32_t aHi = st, aLo = st + P2_ATILE;
        uint32_t bHi = st + 2 * P2_ATILE, bLo = bHi + P2_BTILE;

#pragma unroll
        for (int s = 0; s < 4; s++) {
            int kaB = (s * 16 + (lgrp >> 1) * 8) * 2;
            int kbB = (s * 16 + (lgrp & 1) * 8) * 2;
            uint32_t Ah[2][4], Al[2][4];
            ldmx4(Ah[0], aHi + SWZ(rowA * 128 + kaB));
            ldmx4(Ah[1], aHi + SWZ((rowA + 16) * 128 + kaB));
            ldmx4(Al[0], aLo + SWZ(rowA * 128 + kaB));
            ldmx4(Al[1], aLo + SWZ((rowA + 16) * 128 + kaB));
            uint32_t Bh[2][4], Bl[2][4];
#pragma unroll
            for (int p = 0; p < 2; p++) {
                uint32_t off = SWZ((rowB + p * 16) * 128 + kbB);
                ldmx4(Bh[p], bHi + off);
                ldmx4(Bl[p], bLo + off);
            }
#pragma unroll
            for (int mi = 0; mi < 2; mi++)
#pragma unroll
                for (int nf = 0; nf < 4; nf++) {
                    int p = nf >> 1, h = (nf & 1) * 2;
                    mma16816(acc[mi][nf], Ah[mi], Bh[p][h], Bh[p][h + 1]);
                }
#pragma unroll
            for (int mi = 0; mi < 2; mi++)
#pragma unroll
                for (int nf = 0; nf < 4; nf++) {
                    int p = nf >> 1, h = (nf & 1) * 2;
                    mma16816(acc[mi][nf], Al[mi], Bh[p][h], Bh[p][h + 1]);
                }
#pragma unroll
            for (int mi = 0; mi < 2; mi++)
#pragma unroll
                for (int nf = 0; nf < 4; nf++) {
                    int p = nf >> 1, h = (nf & 1) * 2;
                    mma16816(acc[mi][nf], Ah[mi], Bl[p][h], Bl[p][h + 1]);
                }
        }
    }

    int r4 = lane >> 2, c2 = (lane & 3) * 2;
#pragma unroll
    for (int mi = 0; mi < 2; mi++) {
#pragma unroll
        for (int half = 0; half < 2; half++) {
            int row = wm + mi * 16 + half * 8 + r4;
            int gm  = m0 + row;
            if (gm >= mEnd) continue;
            int slot = s_slot[row];
#pragma unroll
            for (int nf = 0; nf < 4; nf++) {
                int col = n0 + wn + nf * 8 + c2;
                float2 v = make_float2(acc[mi][nf][half * 2 + 0], acc[mi][nf][half * 2 + 1]);
                *(float2*)&g_part[(size_t)slot * H_DIM + col] = v;
            }
        }
    }
}

// ---------------- reduce ----------------
__global__ void reduce_kernel(float* __restrict__ out) {
    int i = blockIdx.x * blockDim.x + threadIdx.x;
    int total = T_TOK * H_DIM / 4;
    if (i >= total) return;
    int t  = i / (H_DIM / 4);
    int hc = (i % (H_DIM / 4)) * 4;
    float4 s = make_float4(0.f, 0.f, 0.f, 0.f);
#pragma unroll
    for (int k = 0; k < TK; k++) {
        float4 v = *(const float4*)&g_part[(size_t)(t * TK + k) * H_DIM + hc];
        s.x += v.x; s.y += v.y; s.z += v.z; s.w += v.w;
    }
    *(float4*)&out[(size_t)t * H_DIM + hc] = s;
}

// ---------------- launch ----------------
extern "C" void kernel_launch(void* const* d_in, const int* in_sizes, int n_in,
                              void* d_out, int out_size)
{
    const float* x             = (const float*)d_in[0];
    const float* router_logits = (const float*)d_in[1];
    const float* w_up          = (const float*)d_in[2];
    const float* w_gate        = (const float*)d_in[3];
    const float* w_down        = (const float*)d_in[4];
    float* out = (float*)d_out;

    cudaFuncSetAttribute(pass1_mma, cudaFuncAttributeMaxDynamicSharedMemorySize, P1_SMEM);
    cudaFuncSetAttribute(pass2_mma, cudaFuncAttributeMaxDynamicSharedMemorySize, P2_SMEM);

    // launch #1: conversions (independent of routing)
    int ntot = NX4 + 3 * NW4;
    conv_all_kernel<<<(ntot + 255) / 256, 256>>>(
        (const float4*)x, (const float4*)w_up, (const float4*)w_gate, (const float4*)w_down);

    // launch #2: fused routing
    routing_kernel<<<1, 1024>>>(router_logits);

    // launch #3: pass1
    dim3 g1(I_DIM / 64, T_TOK / 128, NE);
    pass1_mma<<<g1, 256, P1_SMEM>>>();

    // launch #4: pass2 (profiled slot)
    dim3 g2(H_DIM / 64, T_TOK / 128, NE);
    pass2_mma<<<g2, 256, P2_SMEM>>>();

    // launch #5: reduce
    reduce_kernel<<<(T_TOK * H_DIM / 4 + 255) / 256, 256>>>(out);
}

// round 6
// speedup vs baseline: 1.1163x; 1.1163x over previous
#include <cuda_runtime.h>
#include <cuda_bf16.h>
#include <math.h>
#include <stdint.h>

// Problem constants
#define T_TOK 2048
#define H_DIM 1024
#define I_DIM 512
#define NE    16
#define TK    4
#define NPAIR (T_TOK * TK)   // 8192

// ---------------- scratch (device globals; no allocation) ----------------
__device__ int   g_offsets[NE + 1];
__device__ int   g_ids[NPAIR];
__device__ float g_wt[NPAIR];
__device__ int   g_slot[NPAIR];

__device__ __align__(16) __nv_bfloat16 g_xhi[T_TOK * H_DIM];
__device__ __align__(16) __nv_bfloat16 g_xlo[T_TOK * H_DIM];
__device__ __align__(16) __nv_bfloat16 g_wu_hi[NE * I_DIM * H_DIM];
__device__ __align__(16) __nv_bfloat16 g_wu_lo[NE * I_DIM * H_DIM];
__device__ __align__(16) __nv_bfloat16 g_wg_hi[NE * I_DIM * H_DIM];
__device__ __align__(16) __nv_bfloat16 g_wg_lo[NE * I_DIM * H_DIM];
__device__ __align__(16) __nv_bfloat16 g_wd_hi[NE * H_DIM * I_DIM];
__device__ __align__(16) __nv_bfloat16 g_wd_lo[NE * H_DIM * I_DIM];
__device__ __align__(16) __nv_bfloat16 g_hhi[(size_t)NPAIR * I_DIM];
__device__ __align__(16) __nv_bfloat16 g_hlo[(size_t)NPAIR * I_DIM];
__device__ __align__(16) float g_part[(size_t)NPAIR * H_DIM];   // 32 MB

// ---------------- helpers ----------------
__device__ __forceinline__ uint32_t smem_u32(const void* p) {
    uint32_t a;
    asm("{ .reg .u64 t; cvta.to.shared.u64 t, %1; cvt.u32.u64 %0, t; }" : "=r"(a) : "l"(p));
    return a;
}
__device__ __forceinline__ void cp_async16(uint32_t dst, const void* src) {
    asm volatile("cp.async.cg.shared.global [%0], [%1], 16;" :: "r"(dst), "l"(src));
}
__device__ __forceinline__ void ldmx4(uint32_t r[4], uint32_t addr) {
    asm volatile("ldmatrix.sync.aligned.m8n8.x4.shared.b16 {%0,%1,%2,%3}, [%4];"
                 : "=r"(r[0]), "=r"(r[1]), "=r"(r[2]), "=r"(r[3]) : "r"(addr));
}
__device__ __forceinline__ void mma16816(float d[4], const uint32_t a[4], uint32_t b0, uint32_t b1) {
    asm("mma.sync.aligned.m16n8k16.row.col.f32.bf16.bf16.f32 "
        "{%0,%1,%2,%3}, {%4,%5,%6,%7}, {%8,%9}, {%0,%1,%2,%3};"
        : "+f"(d[0]), "+f"(d[1]), "+f"(d[2]), "+f"(d[3])
        : "r"(a[0]), "r"(a[1]), "r"(a[2]), "r"(a[3]), "r"(b0), "r"(b1));
}
#define SWZ(o) ((o) ^ (((o) >> 3) & 0x70))

// ---------------- kernel: fused routing (router + scan + scatter), 1 block ----------------
__global__ void __launch_bounds__(1024) routing_kernel(const float* __restrict__ logits) {
    __shared__ int s_cnt[NE], s_cur[NE], s_off[NE + 1];
    int tid = threadIdx.x;
    if (tid < NE) { s_cnt[tid] = 0; s_cur[tid] = 0; }
    __syncthreads();

    for (int t = tid; t < T_TOK; t += 1024) {
        float l[NE];
#pragma unroll
        for (int e = 0; e < NE; e++) l[e] = logits[t * NE + e];
        int ids[TK]; float vals[TK];
        unsigned mask = 0;
#pragma unroll
        for (int k = 0; k < TK; k++) {
            float best = -1e30f; int bi = 0;
#pragma unroll
            for (int e = 0; e < NE; e++)
                if (!((mask >> e) & 1u) && l[e] > best) { best = l[e]; bi = e; }
            ids[k] = bi; vals[k] = best; mask |= (1u << bi);
        }
        float m = vals[0];
        float w[TK]; float s = 0.f;
#pragma unroll
        for (int k = 0; k < TK; k++) { w[k] = expf(vals[k] - m); s += w[k]; }
        float inv = 1.f / s;
#pragma unroll
        for (int k = 0; k < TK; k++) {
            g_ids[t * TK + k] = ids[k];
            g_wt[t * TK + k]  = w[k] * inv;
            atomicAdd(&s_cnt[ids[k]], 1);
        }
    }
    __syncthreads();
    if (tid == 0) {
        int acc = 0;
        s_off[0] = 0; g_offsets[0] = 0;
#pragma unroll
        for (int e = 0; e < NE; e++) {
            acc += s_cnt[e];
            s_off[e + 1] = acc;
            g_offsets[e + 1] = acc;
        }
    }
    __syncthreads();
    for (int t = tid; t < T_TOK; t += 1024) {
#pragma unroll
        for (int k = 0; k < TK; k++) {
            int e = g_ids[t * TK + k];
            int pos = s_off[e] + atomicAdd(&s_cur[e], 1);
            g_slot[pos] = t * TK + k;
        }
    }
}

// ---------------- tiny spacer so the profiler's 4th-launch slot = pass1 ----------------
__global__ void noop_kernel() {}

// ---------------- kernel: fused fp32 -> bf16 hi/lo split for all 4 tensors ----------------
#define NX4 (T_TOK * H_DIM / 4)
#define NW4 (NE * I_DIM * H_DIM / 4)
__global__ void conv_all_kernel(const float4* __restrict__ x,
                                const float4* __restrict__ wu,
                                const float4* __restrict__ wg,
                                const float4* __restrict__ wd) {
    int i = blockIdx.x * blockDim.x + threadIdx.x;
    const float4* src; __nv_bfloat16* hi; __nv_bfloat16* lo; int idx;
    if (i < NX4)                { src = x;  hi = g_xhi;  lo = g_xlo;  idx = i; }
    else if (i < NX4 + NW4)     { src = wu; hi = g_wu_hi; lo = g_wu_lo; idx = i - NX4; }
    else if (i < NX4 + 2 * NW4) { src = wg; hi = g_wg_hi; lo = g_wg_lo; idx = i - NX4 - NW4; }
    else if (i < NX4 + 3 * NW4) { src = wd; hi = g_wd_hi; lo = g_wd_lo; idx = i - NX4 - 2 * NW4; }
    else return;
    float4 v = src[idx];
    __nv_bfloat16 h0 = __float2bfloat16_rn(v.x);
    __nv_bfloat16 h1 = __float2bfloat16_rn(v.y);
    __nv_bfloat16 h2 = __float2bfloat16_rn(v.z);
    __nv_bfloat16 h3 = __float2bfloat16_rn(v.w);
    __nv_bfloat16 l0 = __float2bfloat16_rn(v.x - __bfloat162float(h0));
    __nv_bfloat16 l1 = __float2bfloat16_rn(v.y - __bfloat162float(h1));
    __nv_bfloat16 l2 = __float2bfloat16_rn(v.z - __bfloat162float(h2));
    __nv_bfloat16 l3 = __float2bfloat16_rn(v.w - __bfloat162float(h3));
    *(__nv_bfloat162*)&hi[4 * idx + 0] = __halves2bfloat162(h0, h1);
    *(__nv_bfloat162*)&hi[4 * idx + 2] = __halves2bfloat162(h2, h3);
    *(__nv_bfloat162*)&lo[4 * idx + 0] = __halves2bfloat162(l0, l1);
    *(__nv_bfloat162*)&lo[4 * idx + 2] = __halves2bfloat162(l2, l3);
}

// ============================================================================
// pass1: grouped HMMA GEMM, CTA 64x64, K=1024, fused up+gate, 3-term split
// 2-stage, dual-sync, 99KB smem -> 2 CTAs/SM
// ============================================================================
#define P1_ATILE 8192                           // 64 rows x 128B
#define P1_BTILE 8192                           // 64 rows x 128B
#define P1_STAGE (2 * P1_ATILE + 4 * P1_BTILE)  // 49152
#define P1_SMEM  (1024 + 2 * P1_STAGE)          // 99328 -> 2 CTAs/SM
#define P1_NC    16

__device__ __forceinline__ void p1_load(uint32_t st, int k0, int e, int n0,
                                        const int* s_tok, int tid) {
    for (int i = tid; i < 1024; i += 256) {
        int sel = i >> 9, r = (i >> 3) & 63, q = i & 7;
        const __nv_bfloat16* src = (sel ? g_xlo : g_xhi) + (size_t)s_tok[r] * H_DIM + k0 + q * 8;
        cp_async16(st + sel * P1_ATILE + SWZ(r * 128 + q * 16), src);
    }
    for (int i = tid; i < 2048; i += 256) {
        int sel = i >> 9, r = (i >> 3) & 63, q = i & 7;
        const __nv_bfloat16* base =
            (sel == 0) ? g_wu_hi : (sel == 1) ? g_wu_lo : (sel == 2) ? g_wg_hi : g_wg_lo;
        const __nv_bfloat16* src = base + ((size_t)e * I_DIM + n0 + r) * H_DIM + k0 + q * 8;
        cp_async16(st + 2 * P1_ATILE + sel * P1_BTILE + SWZ(r * 128 + q * 16), src);
    }
    asm volatile("cp.async.commit_group;" ::: "memory");
}

__global__ void __launch_bounds__(256, 2) pass1_mma() {
    int e     = blockIdx.z;
    int mBase = g_offsets[e];
    int mEnd  = g_offsets[e + 1];
    int m0    = mBase + blockIdx.y * 64;
    if (m0 >= mEnd) return;
    int n0 = blockIdx.x * 64;

    extern __shared__ char smem[];
    int*   s_tok = (int*)smem;            // 64 ints
    float* s_wt  = (float*)(smem + 256);  // 64 floats
    uint32_t tb  = smem_u32(smem + 1024);

    int tid = threadIdx.x, wid = tid >> 5, lane = tid & 31;
    for (int r = tid; r < 64; r += 256) {
        int gm = m0 + r;
        int slot = (gm < mEnd) ? g_slot[gm] : g_slot[mBase];
        s_tok[r] = slot >> 2;
        s_wt[r]  = g_wt[slot];
    }
    __syncthreads();

    float accU[2][2][4], accG[2][2][4];
#pragma unroll
    for (int a = 0; a < 2; a++)
#pragma unroll
        for (int b = 0; b < 2; b++)
#pragma unroll
            for (int c = 0; c < 4; c++) { accU[a][b][c] = 0.f; accG[a][b][c] = 0.f; }

    int wm = (wid >> 2) * 32;     // warp m offset: 0 or 32
    int wn = (wid & 3) * 16;      // warp n offset: 0,16,32,48
    int lgrp = lane >> 3, lr = lane & 7;
    int rowA = wm + (lgrp & 1) * 8 + lr;
    int rowB = wn + (lgrp >> 1) * 8 + lr;

    // prologue: chunk 0 into stage 0
    p1_load(tb, 0, e, n0, s_tok, tid);

    for (int c = 0; c < P1_NC; c++) {
        if (c + 1 < P1_NC) {
            p1_load(tb + ((c + 1) & 1) * P1_STAGE, (c + 1) * 64, e, n0, s_tok, tid);
            asm volatile("cp.async.wait_group 1;" ::: "memory");
        } else {
            asm volatile("cp.async.wait_group 0;" ::: "memory");
        }
        __syncthreads();

        uint32_t st  = tb + (c & 1) * P1_STAGE;
        uint32_t aHi = st, aLo = st + P1_ATILE;
        uint32_t bU0 = st + 2 * P1_ATILE;            // up hi
        uint32_t bU1 = bU0 + P1_BTILE;               // up lo
        uint32_t bG0 = bU0 + 2 * P1_BTILE;           // gate hi
        uint32_t bG1 = bU0 + 3 * P1_BTILE;           // gate lo

#pragma unroll
        for (int s = 0; s < 4; s++) {
            int kaB = (s * 16 + (lgrp >> 1) * 8) * 2;   // A k byte offset
            int kbB = (s * 16 + (lgrp & 1) * 8) * 2;    // B k byte offset
            uint32_t Ah[2][4], Al[2][4];
            ldmx4(Ah[0], aHi + SWZ(rowA * 128 + kaB));
            ldmx4(Ah[1], aHi + SWZ((rowA + 16) * 128 + kaB));
            ldmx4(Al[0], aLo + SWZ(rowA * 128 + kaB));
            ldmx4(Al[1], aLo + SWZ((rowA + 16) * 128 + kaB));
            uint32_t Uh[4], Ul[4], Gh[4], Gl[4];
            {
                uint32_t off = SWZ(rowB * 128 + kbB);
                ldmx4(Uh, bU0 + off);
                ldmx4(Ul, bU1 + off);
                ldmx4(Gh, bG0 + off);
                ldmx4(Gl, bG1 + off);
            }
            // term-major: independent MMAs between accumulator reuses
#pragma unroll
            for (int mi = 0; mi < 2; mi++)
#pragma unroll
                for (int nf = 0; nf < 2; nf++) {
                    mma16816(accU[mi][nf], Ah[mi], Uh[nf * 2], Uh[nf * 2 + 1]);
                    mma16816(accG[mi][nf], Ah[mi], Gh[nf * 2], Gh[nf * 2 + 1]);
                }
#pragma unroll
            for (int mi = 0; mi < 2; mi++)
#pragma unroll
                for (int nf = 0; nf < 2; nf++) {
                    mma16816(accU[mi][nf], Al[mi], Uh[nf * 2], Uh[nf * 2 + 1]);
                    mma16816(accG[mi][nf], Al[mi], Gh[nf * 2], Gh[nf * 2 + 1]);
                }
#pragma unroll
            for (int mi = 0; mi < 2; mi++)
#pragma unroll
                for (int nf = 0; nf < 2; nf++) {
                    mma16816(accU[mi][nf], Ah[mi], Ul[nf * 2], Ul[nf * 2 + 1]);
                    mma16816(accG[mi][nf], Ah[mi], Gl[nf * 2], Gl[nf * 2 + 1]);
                }
        }
        __syncthreads();
    }

    // ---- epilogue: h = w * silu(w*g) * (w*u), re-split into bf16 hi/lo ----
    int r4 = lane >> 2, c2 = (lane & 3) * 2;
#pragma unroll
    for (int mi = 0; mi < 2; mi++) {
#pragma unroll
        for (int half = 0; half < 2; half++) {
            int row = wm + mi * 16 + half * 8 + r4;
            int gm  = m0 + row;
            if (gm >= mEnd) continue;
            float w = s_wt[row];
#pragma unroll
            for (int nf = 0; nf < 2; nf++) {
                int col = n0 + wn + nf * 8 + c2;
                float u0 = w * accU[mi][nf][half * 2 + 0];
                float u1 = w * accU[mi][nf][half * 2 + 1];
                float gg0 = w * accG[mi][nf][half * 2 + 0];
                float gg1 = w * accG[mi][nf][half * 2 + 1];
                float r0 = w * (gg0 / (1.f + expf(-gg0))) * u0;
                float r1 = w * (gg1 / (1.f + expf(-gg1))) * u1;
                __nv_bfloat16 h0 = __float2bfloat16_rn(r0);
                __nv_bfloat16 h1 = __float2bfloat16_rn(r1);
                __nv_bfloat16 l0 = __float2bfloat16_rn(r0 - __bfloat162float(h0));
                __nv_bfloat16 l1 = __float2bfloat16_rn(r1 - __bfloat162float(h1));
                *(__nv_bfloat162*)&g_hhi[(size_t)gm * I_DIM + col] = __halves2bfloat162(h0, h1);
                *(__nv_bfloat162*)&g_hlo[(size_t)gm * I_DIM + col] = __halves2bfloat162(l0, l1);
            }
        }
    }
}

// ============================================================================
// pass2: grouped HMMA GEMM h @ w_down^T, CTA 128x64, K=512, 3-term split
// 2-stage, dual-sync, 99KB smem -> 2 CTAs/SM  (R4 configuration)
// ============================================================================
#define P2_ATILE 16384
#define P2_BTILE 8192
#define P2_STAGE (2 * P2_ATILE + 2 * P2_BTILE)  // 49152
#define P2_SMEM  (1024 + 2 * P2_STAGE)          // 99328
#define P2_NC    8

__device__ __forceinline__ void p2_load(uint32_t st, int k0, int e, int n0,
                                        const int* s_row, int tid) {
    for (int i = tid; i < 2048; i += 256) {
        int sel = i >> 10, r = (i >> 3) & 127, q = i & 7;
        const __nv_bfloat16* src = (sel ? g_hlo : g_hhi) + (size_t)s_row[r] * I_DIM + k0 + q * 8;
        cp_async16(st + sel * P2_ATILE + SWZ(r * 128 + q * 16), src);
    }
    for (int i = tid; i < 1024; i += 256) {
        int sel = i >> 9, r = (i >> 3) & 63, q = i & 7;
        const __nv_bfloat16* base = sel ? g_wd_lo : g_wd_hi;
        const __nv_bfloat16* src = base + ((size_t)e * H_DIM + n0 + r) * I_DIM + k0 + q * 8;
        cp_async16(st + 2 * P2_ATILE + sel * P2_BTILE + SWZ(r * 128 + q * 16), src);
    }
    asm volatile("cp.async.commit_group;" ::: "memory");
}

__global__ void __launch_bounds__(256, 2) pass2_mma() {
    int e     = blockIdx.z;
    int mBase = g_offsets[e];
    int mEnd  = g_offsets[e + 1];
    int m0    = mBase + blockIdx.y * 128;
    if (m0 >= mEnd) return;
    int n0 = blockIdx.x * 64;

    extern __shared__ char smem[];
    int* s_row  = (int*)smem;
    int* s_slot = (int*)(smem + 512);
    uint32_t tb = smem_u32(smem + 1024);

    int tid = threadIdx.x, wid = tid >> 5, lane = tid & 31;
    for (int r = tid; r < 128; r += 256) {
        int gm = m0 + r;
        s_row[r]  = (gm < mEnd) ? gm : mBase;
        s_slot[r] = (gm < mEnd) ? g_slot[gm] : 0;
    }
    __syncthreads();

    float acc[2][4][4];
#pragma unroll
    for (int a = 0; a < 2; a++)
#pragma unroll
        for (int b = 0; b < 4; b++)
#pragma unroll
            for (int c = 0; c < 4; c++) acc[a][b][c] = 0.f;

    int wm = (wid >> 1) * 32;
    int wn = (wid & 1) * 32;
    int lgrp = lane >> 3, lr = lane & 7;
    int rowA = wm + (lgrp & 1) * 8 + lr;
    int rowB = wn + (lgrp >> 1) * 8 + lr;

    p2_load(tb, 0, e, n0, s_row, tid);

    for (int c = 0; c < P2_NC; c++) {
        if (c + 1 < P2_NC) {
            p2_load(tb + ((c + 1) & 1) * P2_STAGE, (c + 1) * 64, e, n0, s_row, tid);
            asm volatile("cp.async.wait_group 1;" ::: "memory");
        } else {
            asm volatile("cp.async.wait_group 0;" ::: "memory");
        }
        __syncthreads();

        uint32_t st  = tb + (c & 1) * P2_STAGE;
        uint32_t aHi = st, aLo = st + P2_ATILE;
        uint32_t bHi = st + 2 * P2_ATILE, bLo = bHi + P2_BTILE;

#pragma unroll
        for (int s = 0; s < 4; s++) {
            int kaB = (s * 16 + (lgrp >> 1) * 8) * 2;
            int kbB = (s * 16 + (lgrp & 1) * 8) * 2;
            uint32_t Ah[2][4], Al[2][4];
            ldmx4(Ah[0], aHi + SWZ(rowA * 128 + kaB));
            ldmx4(Ah[1], aHi + SWZ((rowA + 16) * 128 + kaB));
            ldmx4(Al[0], aLo + SWZ(rowA * 128 + kaB));
            ldmx4(Al[1], aLo + SWZ((rowA + 16) * 128 + kaB));
            uint32_t Bh[2][4], Bl[2][4];
#pragma unroll
            for (int p = 0; p < 2; p++) {
                uint32_t off = SWZ((rowB + p * 16) * 128 + kbB);
                ldmx4(Bh[p], bHi + off);
                ldmx4(Bl[p], bLo + off);
            }
#pragma unroll
            for (int mi = 0; mi < 2; mi++)
#pragma unroll
                for (int nf = 0; nf < 4; nf++) {
                    int p = nf >> 1, h = (nf & 1) * 2;
                    mma16816(acc[mi][nf], Ah[mi], Bh[p][h], Bh[p][h + 1]);
                }
#pragma unroll
            for (int mi = 0; mi < 2; mi++)
#pragma unroll
                for (int nf = 0; nf < 4; nf++) {
                    int p = nf >> 1, h = (nf & 1) * 2;
                    mma16816(acc[mi][nf], Al[mi], Bh[p][h], Bh[p][h + 1]);
                }
#pragma unroll
            for (int mi = 0; mi < 2; mi++)
#pragma unroll
                for (int nf = 0; nf < 4; nf++) {
                    int p = nf >> 1, h = (nf & 1) * 2;
                    mma16816(acc[mi][nf], Ah[mi], Bl[p][h], Bl[p][h + 1]);
                }
        }
        __syncthreads();
    }

    int r4 = lane >> 2, c2 = (lane & 3) * 2;
#pragma unroll
    for (int mi = 0; mi < 2; mi++) {
#pragma unroll
        for (int half = 0; half < 2; half++) {
            int row = wm + mi * 16 + half * 8 + r4;
            int gm  = m0 + row;
            if (gm >= mEnd) continue;
            int slot = s_slot[row];
#pragma unroll
            for (int nf = 0; nf < 4; nf++) {
                int col = n0 + wn + nf * 8 + c2;
                float2 v = make_float2(acc[mi][nf][half * 2 + 0], acc[mi][nf][half * 2 + 1]);
                *(float2*)&g_part[(size_t)slot * H_DIM + col] = v;
            }
        }
    }
}

// ---------------- reduce ----------------
__global__ void reduce_kernel(float* __restrict__ out) {
    int i = blockIdx.x * blockDim.x + threadIdx.x;
    int total = T_TOK * H_DIM / 4;
    if (i >= total) return;
    int t  = i / (H_DIM / 4);
    int hc = (i % (H_DIM / 4)) * 4;
    float4 s = make_float4(0.f, 0.f, 0.f, 0.f);
#pragma unroll
    for (int k = 0; k < TK; k++) {
        float4 v = *(const float4*)&g_part[(size_t)(t * TK + k) * H_DIM + hc];
        s.x += v.x; s.y += v.y; s.z += v.z; s.w += v.w;
    }
    *(float4*)&out[(size_t)t * H_DIM + hc] = s;
}

// ---------------- launch ----------------
extern "C" void kernel_launch(void* const* d_in, const int* in_sizes, int n_in,
                              void* d_out, int out_size)
{
    const float* x             = (const float*)d_in[0];
    const float* router_logits = (const float*)d_in[1];
    const float* w_up          = (const float*)d_in[2];
    const float* w_gate        = (const float*)d_in[3];
    const float* w_down        = (const float*)d_in[4];
    float* out = (float*)d_out;

    cudaFuncSetAttribute(pass1_mma, cudaFuncAttributeMaxDynamicSharedMemorySize, P1_SMEM);
    cudaFuncSetAttribute(pass2_mma, cudaFuncAttributeMaxDynamicSharedMemorySize, P2_SMEM);

    // #1 routing, #2 conversions, #3 spacer, #4 pass1 (profiled), #5 pass2, #6 reduce
    routing_kernel<<<1, 1024>>>(router_logits);

    int ntot = NX4 + 3 * NW4;
    conv_all_kernel<<<(ntot + 255) / 256, 256>>>(
        (const float4*)x, (const float4*)w_up, (const float4*)w_gate, (const float4*)w_down);

    noop_kernel<<<1, 32>>>();

    dim3 g1(I_DIM / 64, T_TOK / 64, NE);
    pass1_mma<<<g1, 256, P1_SMEM>>>();

    dim3 g2(H_DIM / 64, T_TOK / 128, NE);
    pass2_mma<<<g2, 256, P2_SMEM>>>();

    reduce_kernel<<<(T_TOK * H_DIM / 4 + 255) / 256, 256>>>(out);
}